// round 7
// baseline (speedup 1.0000x reference)
#include <cuda_runtime.h>
#include <cuda_fp16.h>
#include <mma.h>
#include <cstdint>

using namespace nvcuda;
typedef __half h16;

#define BB   128
#define NN   36
#define FEATD 2048
#define MIDD 517
#define HIDD 128
#define OUTD 1024
#define G4   4096
#define KP2  544
#define TSTEPS 36
#define NBLK_STEPS 128

// ---- fp16 core geometry: 128x64 tile, 8 warps (4M x 2N), k-chunk 32 ----
#define C_LD  40                         // smem row stride in fp16 elems (80B)
#define C_OA  0                          // A hi : 128*80 = 10240
#define C_OBH 10240                      // B hi : 64*80 = 5120
#define C_OBL 15360                      // B lo : 5120
#define C_STG 20480
#define C_DYN (3 * C_STG)                // 61440 bytes

// ---- fused skew+assign smem layout (floats) ----
#define SA_SF   0
#define SA_SWX  1152
#define SA_SWY  5376
#define SA_HX   9600
#define SA_HY   14208
#define SA_OUT  18816
#define SA_CS   20112
#define SA_LG   21408
#define SA_PS   22704
#define SA_DS   24000
#define SA_SA   25296
#define SA_W2   25332
#define SA_B1   25460
#define SA_TOT  25588
#define SA_DYN  (SA_TOT * 4)

// ------------------------- scratch -------------------------
__device__ float g_scale[BB];
__device__ float g_sigatt[BB * NN];
__device__ float g_feats[BB * MIDD * NN];                 // [b][m][n] fp32

__device__ __align__(16) h16 g_feat_hi[(size_t)BB * NN * FEATD];
__device__ __align__(16) h16 g_feat_lo[(size_t)BB * NN * FEATD];
__device__ __align__(16) h16 g_convw_h[512 * FEATD];
__device__ __align__(16) h16 g_wih_hi[(size_t)G4 * KP2];    // col = u*4+g
__device__ __align__(16) h16 g_wih_lo[(size_t)G4 * KP2];
__device__ __align__(16) h16 g_whh_h[(size_t)G4 * OUTD];    // reordered
__device__ __align__(16) h16 g_xh[(size_t)TSTEPS * BB * KP2];
__device__ float g_gates_in[(size_t)TSTEPS * BB * G4];      // reordered cols
__device__ __align__(16) h16 g_h0[BB * OUTD];
__device__ __align__(16) h16 g_h1[BB * OUTD];
__device__ float g_c[BB * OUTD];
__device__ __align__(16) float g_part[BB][G4];              // kz1 partials
__device__ unsigned g_flag[64];                              // per-ntile step flag
__device__ unsigned g_done;                                  // grid barrier

// ------------------------- helpers -------------------------
__device__ __forceinline__ void split_write(float v, h16* hi, h16* lo) {
    h16 h = __float2half(v);
    *hi = h;
    *lo = __float2half(v - __half2float(h));
}

__device__ __forceinline__ void cp16(void* dst, const void* src) {
    unsigned d = (unsigned)__cvta_generic_to_shared(dst);
    asm volatile("cp.async.ca.shared.global [%0], [%1], 16;\n" ::"r"(d), "l"(src));
}
__device__ __forceinline__ void cp16cg(void* dst, const void* src) {
    unsigned d = (unsigned)__cvta_generic_to_shared(dst);
    asm volatile("cp.async.cg.shared.global [%0], [%1], 16;\n" ::"r"(d), "l"(src));
}

// ------------------------- init + scale -------------------------
__global__ void k_init(const float* __restrict__ boxes) {
    int idx = blockIdx.x * blockDim.x + threadIdx.x;
    if (idx < 64) g_flag[idx] = 0;
    if (idx == 64) g_done = 0;
    if (idx < BB) {
        const float* p = boxes + (size_t)idx * 4 * NN;
        float m = -1e30f;
        for (int i = 0; i < 4 * NN; i++) m = fmaxf(m, p[i]);
        g_scale[idx] = m;
    }
    if (idx < BB * OUTD) {
        g_h0[idx] = __float2half(0.f);
        g_c[idx] = 0.f;
    }
}

__global__ void k_head(const float* __restrict__ boxes,
                       const float* __restrict__ att) {
    int idx = blockIdx.x * blockDim.x + threadIdx.x;
    if (idx >= BB * NN) return;
    int b = idx / NN, n = idx - b * NN;
    float inv = 1.f / g_scale[b];
    for (int r = 0; r < 4; r++)
        g_feats[(size_t)b * MIDD * NN + r * NN + n] =
            boxes[(size_t)b * 4 * NN + r * NN + n] * inv;
    float a = att[idx];
    g_feats[(size_t)b * MIDD * NN + 4 * NN + n] = a;
    g_sigatt[idx] = 1.f / (1.f + expf(-a));
}

// ------------------------- fused weight/feature prep ------------------------
#define PN1 ((size_t)512 * FEATD)
#define PN2 ((size_t)G4 * KP2)
#define PN3 ((size_t)G4 * OUTD)
#define PN4 ((size_t)BB * NN * FEATD)
__global__ void k_prep(const float* __restrict__ cw, const float* __restrict__ wih,
                       const float* __restrict__ whh, const float* __restrict__ feat) {
    size_t idx = (size_t)blockIdx.x * blockDim.x + threadIdx.x;
    if (idx < PN1) {
        g_convw_h[idx] = __float2half(cw[idx]);
    } else if (idx < PN1 + PN2) {
        size_t i = idx - PN1;
        int cr = (int)(i / KP2), k = (int)(i - (size_t)cr * KP2);
        int u = cr >> 2, g = cr & 3;
        float v = (k < MIDD) ? wih[(size_t)(g * OUTD + u) * MIDD + k] : 0.f;
        split_write(v, &g_wih_hi[i], &g_wih_lo[i]);
    } else if (idx < PN1 + PN2 + PN3) {
        size_t i = idx - PN1 - PN2;
        int cr = (int)(i / OUTD), k = (int)(i - (size_t)cr * OUTD);
        int u = cr >> 2, g = cr & 3;
        g_whh_h[i] = __float2half(whh[(size_t)(g * OUTD + u) * OUTD + k]);
    } else if (idx < PN1 + PN2 + PN3 + PN4) {
        size_t i = idx - PN1 - PN2 - PN3;
        split_write(feat[i], &g_feat_hi[i], &g_feat_lo[i]);
    }
}

// ------------------------- fp16 GEMM core: 128x64 tile, 256 thr -------------
// NT=2: C = Ah * (Bh+Bl)^T ; NT=1: C = Ah * Bh^T.  ACG=1: A via cp.async.cg.
template <int NT, int ACG>
__device__ __forceinline__ float* gemm_core(
    const h16* __restrict__ Ah,
    const h16* __restrict__ Bh, const h16* __restrict__ Bl,
    int lda, int ldb, int nch, int m0, int n0, int kbeg, char* sm)
{
    const int t = threadIdx.x, w = t >> 5;
    const int wm = w >> 1, wn = w & 1;

    wmma::fragment<wmma::accumulator, 16, 16, 16, float> acc[2][2];
#pragma unroll
    for (int i = 0; i < 2; i++)
#pragma unroll
        for (int j = 0; j < 2; j++) wmma::fill_fragment(acc[i][j], 0.f);

    auto issue = [&](int jc) {
        char* st = sm + (jc % 3) * C_STG;
        int k0 = kbeg + jc * 32;
        const int NSEG = (NT == 2) ? 4 : 3;
#pragma unroll
        for (int u = 0; u < NSEG; u++) {
            int seg = t + u * 256;
            if (seg < 512) {
                int row = seg >> 2, s = seg & 3;
                const h16* src = Ah + (size_t)(m0 + row) * lda + k0 + s * 8;
                char* dst = st + C_OA + row * 80 + s * 16;
                if (ACG) cp16cg(dst, src); else cp16(dst, src);
            } else if (seg < 768) {
                int x = seg - 512;
                int row = x >> 2, s = x & 3;
                cp16(st + C_OBH + row * 80 + s * 16,
                     Bh + (size_t)(n0 + row) * ldb + k0 + s * 8);
            } else {
                int x = seg - 768;
                int row = x >> 2, s = x & 3;
                cp16(st + C_OBL + row * 80 + s * 16,
                     Bl + (size_t)(n0 + row) * ldb + k0 + s * 8);
            }
        }
        asm volatile("cp.async.commit_group;\n" ::: "memory");
    };

    issue(0);
    issue(1);
    for (int i = 0; i < nch; i++) {
        if (i < nch - 1)
            asm volatile("cp.async.wait_group 1;\n" ::: "memory");
        else
            asm volatile("cp.async.wait_group 0;\n" ::: "memory");
        __syncthreads();
        if (i + 2 < nch) issue(i + 2);

        char* st = sm + (i % 3) * C_STG;
        h16* sA = (h16*)(st + C_OA);
        h16* sBh = (h16*)(st + C_OBH);
        h16* sBl = (h16*)(st + C_OBL);
#pragma unroll
        for (int ks = 0; ks < 2; ks++) {
            const int kk = ks * 16;
            wmma::fragment<wmma::matrix_a, 16, 16, 16, h16, wmma::row_major> a[2];
            wmma::fragment<wmma::matrix_b, 16, 16, 16, h16, wmma::col_major> bh[2];
#pragma unroll
            for (int i2 = 0; i2 < 2; i2++) {
                wmma::load_matrix_sync(a[i2], &sA[(wm * 32 + i2 * 16) * C_LD + kk], C_LD);
                wmma::load_matrix_sync(bh[i2], &sBh[(wn * 32 + i2 * 16) * C_LD + kk], C_LD);
            }
#pragma unroll
            for (int i2 = 0; i2 < 2; i2++)
#pragma unroll
                for (int j2 = 0; j2 < 2; j2++)
                    wmma::mma_sync(acc[i2][j2], a[i2], bh[j2], acc[i2][j2]);
            if (NT == 2) {
                wmma::fragment<wmma::matrix_b, 16, 16, 16, h16, wmma::col_major> bl[2];
#pragma unroll
                for (int i2 = 0; i2 < 2; i2++)
                    wmma::load_matrix_sync(bl[i2], &sBl[(wn * 32 + i2 * 16) * C_LD + kk], C_LD);
#pragma unroll
                for (int i2 = 0; i2 < 2; i2++)
#pragma unroll
                    for (int j2 = 0; j2 < 2; j2++)
                        wmma::mma_sync(acc[i2][j2], a[i2], bl[j2], acc[i2][j2]);
            }
        }
    }
    __syncthreads();
    float* Cs = (float*)sm;
#pragma unroll
    for (int i2 = 0; i2 < 2; i2++)
#pragma unroll
        for (int j2 = 0; j2 < 2; j2++)
            wmma::store_matrix_sync(&Cs[(wm * 32 + i2 * 16) * 64 + wn * 32 + j2 * 16],
                                    acc[i2][j2], 64, wmma::mem_row_major);
    __syncthreads();
    return Cs;
}

// ------------------------- conv GEMM -------------------------
__global__ __launch_bounds__(256) void k_conv(const float* __restrict__ convb) {
    extern __shared__ char sm[];
    int m0 = blockIdx.x * 128, n0 = blockIdx.y * 64;
    float* Cs = gemm_core<2, 0>(g_convw_h, g_feat_hi, g_feat_lo,
                                FEATD, FEATD, FEATD / 32, m0, n0, 0, sm);
    for (int idx = threadIdx.x; idx < 128 * 64; idx += 256) {
        int r = idx >> 6, cc = idx & 63;
        int m = m0 + r, col = n0 + cc;
        int b = col / NN, n = col - b * NN;
        g_feats[(size_t)b * MIDD * NN + (5 + m) * NN + n] = Cs[idx] + convb[m];
    }
}

// ------------------------- input-gate GEMM -------------------------
__global__ __launch_bounds__(256) void k_gin(const float* __restrict__ bih,
                                             const float* __restrict__ bhh) {
    extern __shared__ char sm[];
    int m0 = blockIdx.x * 128, n0 = blockIdx.y * 64;
    float* Cs = gemm_core<2, 0>(g_xh, g_wih_hi, g_wih_lo,
                                KP2, KP2, KP2 / 32, m0, n0, 0, sm);
    for (int idx = threadIdx.x; idx < 128 * 64; idx += 256) {
        int r = idx >> 6, cc = idx & 63;
        int row = m0 + r, col = n0 + cc;
        int orig = (col & 3) * OUTD + (col >> 2);
        g_gates_in[(size_t)row * G4 + col] = Cs[idx] + bih[orig] + bhh[orig];
    }
}

// ------------------------- persistent LSTM: 36 steps, 1 launch --------------
__global__ __launch_bounds__(256) void k_steps(float* __restrict__ outc) {
    extern __shared__ char sm[];
    const int bid = blockIdx.x;
    const int kz = bid >> 6;
    const int ntile = bid & 63;
    const int n0 = ntile * 64;
    const int t = threadIdx.x;

    for (int s = 0; s < TSTEPS; s++) {
        const h16* hin = (s & 1) ? g_h1 : g_h0;
        h16* hout = (s & 1) ? g_h0 : g_h1;

        float* Cs = gemm_core<1, 1>(hin, g_whh_h, g_whh_h,
                                    OUTD, OUTD, 16, 0, n0, kz * 512, sm);
        const float4* Cs4 = (const float4*)Cs;

        if (kz == 1) {
            // publish partial, release flag
            float4* dst4 = (float4*)&g_part[0][n0];
            for (int p = t; p < 2048; p += 256)
                dst4[(p >> 4) * (G4 / 4) + (p & 15)] = Cs4[p];
            __threadfence();
            __syncthreads();
            if (t == 0) atomicExch(&g_flag[ntile], (unsigned)(s + 1));
        } else {
            // wait for peer partial, fused epilogue
            if (t == 0) {
                while (*(volatile unsigned*)&g_flag[ntile] < (unsigned)(s + 1)) {}
                __threadfence();
            }
            __syncthreads();
            const float* gin = g_gates_in + (size_t)s * BB * G4;
            for (int p = t; p < 2048; p += 256) {
                int b = p >> 4, lu = p & 15;
                float4 mine = Cs4[p];
                float4 oth = __ldcg((const float4*)&g_part[b][n0 + lu * 4]);
                float4 gv = *(const float4*)(gin + (size_t)b * G4 + n0 + lu * 4);
                float ig = mine.x + oth.x + gv.x;
                float fg = mine.y + oth.y + gv.y;
                float gg = mine.z + oth.z + gv.z;
                float og = mine.w + oth.w + gv.w;
                float si = 1.f / (1.f + expf(-ig));
                float sf = 1.f / (1.f + expf(-fg));
                float so = 1.f / (1.f + expf(-og));
                int u = (n0 >> 2) + lu;
                int ci = b * OUTD + u;
                float c = sf * g_c[ci] + si * tanhf(gg);
                g_c[ci] = c;
                hout[ci] = __float2half(so * tanhf(c));
                if (s == TSTEPS - 1) outc[ci] = c;
            }
        }

        if (s == TSTEPS - 1) break;
        // grid barrier (volatile spin; counters reset by k_init each replay)
        __threadfence();
        __syncthreads();
        if (t == 0) {
            atomicAdd(&g_done, 1u);
            unsigned tgt = (unsigned)NBLK_STEPS * (s + 1);
            while (*(volatile unsigned*)&g_done < tgt) {}
            __threadfence();
        }
        __syncthreads();
    }
}

// ------------------------- fused skew + assignment + mix --------------------
__global__ __launch_bounds__(512) void k_sa(const float* __restrict__ wx,
                                            const float* __restrict__ wy,
                                            const float* __restrict__ b1,
                                            const float* __restrict__ w2,
                                            const float* __restrict__ b2p,
                                            const float* __restrict__ lrp) {
    extern __shared__ float S[];
    int b = blockIdx.x, t = threadIdx.x;
    const float* fb = g_feats + (size_t)b * MIDD * NN;

    // ---- phase 1: skew hx/hy into smem ----
    {
        int h = t & 127, g = t >> 7;     // 4 col-groups of 9
        float ax[9], ay[9];
#pragma unroll
        for (int n = 0; n < 9; n++) { ax[n] = 0.f; ay[n] = 0.f; }
        for (int mc = 0; mc < MIDD; mc += 32) {
            int mlen = min(32, MIDD - mc);
            for (int i = t; i < mlen * NN; i += 512) S[SA_SF + i] = fb[mc * NN + i];
            if (g == 0) {
                for (int j = 0; j < mlen; j++)
                    S[SA_SWX + h * 33 + j] = wx[(size_t)h * MIDD + mc + j];
            } else if (g == 1) {
                for (int j = 0; j < mlen; j++)
                    S[SA_SWY + h * 33 + j] = wy[(size_t)h * MIDD + mc + j];
            }
            __syncthreads();
            for (int j = 0; j < mlen; j++) {
                float wxv = S[SA_SWX + h * 33 + j];
                float wyv = S[SA_SWY + h * 33 + j];
                const float* sr = &S[SA_SF + j * NN + g * 9];
#pragma unroll
                for (int n = 0; n < 9; n++) {
                    float fv = sr[n];
                    ax[n] += wxv * fv;
                    ay[n] += wyv * fv;
                }
            }
            __syncthreads();
        }
#pragma unroll
        for (int n = 0; n < 9; n++) {
            S[SA_HX + h * NN + g * 9 + n] = ax[n];
            S[SA_HY + h * NN + g * 9 + n] = ay[n];
        }
    }
    if (t < 128) { S[SA_W2 + t] = w2[t]; S[SA_B1 + t] = b1[t]; }
    if (t < 36) S[SA_SA + t] = g_sigatt[b * NN + t];
    __syncthreads();

    // ---- phase 2: skew scores + antisymmetrize ----
    float b2v = b2p[0];
    for (int p = t; p < 1296; p += 512) {
        int i = p / 36, j = p - i * 36;
        float s = 0.f;
#pragma unroll 8
        for (int h = 0; h < HIDD; h++) {
            float v = S[SA_HX + h * NN + i] + S[SA_HY + h * NN + j] + S[SA_B1 + h];
            s += S[SA_W2 + h] * fmaxf(v, 0.f);
        }
        S[SA_OUT + p] = s + b2v;
    }
    __syncthreads();
    for (int p = t; p < 1296; p += 512) {
        int i = p / 36, j = p - i * 36;
        S[SA_CS + p] = S[SA_OUT + p] - S[SA_OUT + j * 36 + i];
        S[SA_LG + p] = 0.f;
    }
    __syncthreads();

    // ---- phase 3: 3-iter assignment ----
    float lrabs = fabsf(lrp[0]);
    for (int it = 0; it < 3; it++) {
        if (t < 36) {
            float mx = -1e30f;
            for (int j = 0; j < 36; j++) mx = fmaxf(mx, S[SA_LG + t * 36 + j]);
            float sum = 0.f;
            for (int j = 0; j < 36; j++) {
                float e = expf(S[SA_LG + t * 36 + j] - mx);
                S[SA_PS + t * 36 + j] = e;
                sum += e;
            }
            float inv = 1.f / sum;
            for (int j = 0; j < 36; j++) S[SA_PS + t * 36 + j] *= inv;
        }
        __syncthreads();
        if (t < 36) {
            int l = t;
            float tot = 0.f;
            for (int i = 0; i < 36; i++) tot += S[SA_PS + i * 36 + l];
            float run = 0.f;
            for (int i = 0; i < 36; i++) {
                float p = S[SA_PS + i * 36 + l];
                run += p;
                S[SA_DS + i * 36 + l] = tot - 2.f * run + p;
            }
        }
        __syncthreads();
        for (int p = t; p < 1296; p += 512) {
            int i = p / 36, j = p - i * 36;
            float gsum = 0.f;
#pragma unroll
            for (int l = 0; l < 36; l++)
                gsum += S[SA_DS + i * 36 + l] * S[SA_CS + j * 36 + l];
            S[SA_LG + p] -= lrabs * gsum;
        }
        __syncthreads();
    }
    if (t < 36) {
        float mx = -1e30f;
        for (int j = 0; j < 36; j++) mx = fmaxf(mx, S[SA_LG + t * 36 + j]);
        float sum = 0.f;
        for (int j = 0; j < 36; j++) {
            float e = expf(S[SA_LG + t * 36 + j] - mx);
            S[SA_PS + t * 36 + j] = e;
            sum += e;
        }
        float inv = 1.f / sum;
        for (int j = 0; j < 36; j++) S[SA_PS + t * 36 + j] *= inv;
    }
    __syncthreads();

    // ---- phase 4: permutation mix -> x_seq fp16 ----
    for (int p = t; p < MIDD * NN; p += 512) {
        int c = p / 36, i = p - c * 36;
        float s = 0.f;
#pragma unroll
        for (int l = 0; l < 36; l++)
            s += fb[c * 36 + l] * S[SA_SA + l] * S[SA_PS + i * 36 + l];
        g_xh[((size_t)i * BB + b) * KP2 + c] = __float2half(s);
    }
    for (int p = t; p < (KP2 - MIDD) * NN; p += 512) {
        int c = MIDD + p / 36, i = p % 36;
        g_xh[((size_t)i * BB + b) * KP2 + c] = __float2half(0.f);
    }
}

// ------------------------- launch -------------------------
extern "C" void kernel_launch(void* const* d_in, const int* in_sizes, int n_in,
                              void* d_out, int out_size) {
    const float* boxes     = (const float*)d_in[0];
    const float* attention = (const float*)d_in[1];
    const float* features  = (const float*)d_in[2];
    const float* conv_w    = (const float*)d_in[3];
    const float* conv_b    = (const float*)d_in[4];
    const float* skew_wx   = (const float*)d_in[5];
    const float* skew_wy   = (const float*)d_in[6];
    const float* skew_b1   = (const float*)d_in[7];
    const float* skew_w2   = (const float*)d_in[8];
    const float* skew_b2   = (const float*)d_in[9];
    const float* w_ih      = (const float*)d_in[10];
    const float* w_hh      = (const float*)d_in[11];
    const float* b_ih      = (const float*)d_in[12];
    const float* b_hh      = (const float*)d_in[13];
    const float* lr        = (const float*)d_in[14];

    static int attr_done = 0;
    if (!attr_done) {
        cudaFuncSetAttribute(k_conv,  cudaFuncAttributeMaxDynamicSharedMemorySize, C_DYN);
        cudaFuncSetAttribute(k_gin,   cudaFuncAttributeMaxDynamicSharedMemorySize, C_DYN);
        cudaFuncSetAttribute(k_steps, cudaFuncAttributeMaxDynamicSharedMemorySize, C_DYN);
        cudaFuncSetAttribute(k_sa,    cudaFuncAttributeMaxDynamicSharedMemorySize, SA_DYN);
        attr_done = 1;
    }

    k_init<<<(BB * OUTD + 255) / 256, 256>>>(boxes);
    k_head<<<(BB * NN + 255) / 256, 256>>>(boxes, attention);
    {
        size_t total = PN1 + PN2 + PN3 + PN4;
        k_prep<<<(unsigned)((total + 511) / 512), 512>>>(conv_w, w_ih, w_hh, features);
    }
    k_conv<<<dim3(4, 72), 256, C_DYN>>>(conv_b);
    k_sa<<<BB, 512, SA_DYN>>>(skew_wx, skew_wy, skew_b1, skew_w2, skew_b2, lr);
    k_gin<<<dim3(36, 64), 256, C_DYN>>>(b_ih, b_hh);
    k_steps<<<NBLK_STEPS, 256, C_DYN>>>((float*)d_out);
}

// round 8
// speedup vs baseline: 1.5501x; 1.5501x over previous
#include <cuda_runtime.h>
#include <cuda_fp16.h>
#include <mma.h>
#include <cstdint>

using namespace nvcuda;
typedef __half h16;

#define BB   128
#define NN   36
#define FEATD 2048
#define MIDD 517
#define HIDD 128
#define OUTD 1024
#define G4   4096
#define KP2  576
#define TSTEPS 36

// ---- fp16 core geometry: 128x64 tile, 8 warps (4M x 2N), k-chunk 64 ----
#define C_LD   72                        // smem row stride in fp16 (144B)
#define C_OA   0                         // A: 128*144 = 18432
#define C_OBH  18432                     // B hi: 64*144 = 9216
#define C_OBL  27648                     // B lo: 9216
#define STG2   36864                     // NT=2 stage
#define STG1   27648                     // NT=1 stage
#define DYN2   (3 * STG2)                // 110592
#define DYN1   (3 * STG1)                // 82944

// ---- fused skew+assign smem layout (floats) ----
#define SA_SF   0
#define SA_SWX  1152
#define SA_SWY  5376
#define SA_HX   9600
#define SA_HY   14208
#define SA_OUT  18816
#define SA_CS   20112
#define SA_LG   21408
#define SA_PS   22704
#define SA_DS   24000
#define SA_SA   25296
#define SA_W2   25332
#define SA_B1   25460
#define SA_TOT  25588
#define SA_DYN  (SA_TOT * 4)

// ------------------------- scratch -------------------------
__device__ float g_scale[BB];
__device__ float g_sigatt[BB * NN];
__device__ float g_feats[BB * MIDD * NN];                 // [b][m][n] fp32

__device__ __align__(16) h16 g_feat_hi[(size_t)BB * NN * FEATD];
__device__ __align__(16) h16 g_feat_lo[(size_t)BB * NN * FEATD];
__device__ __align__(16) h16 g_convw_h[512 * FEATD];
__device__ __align__(16) h16 g_wih_hi[(size_t)G4 * KP2];    // col = u*4+g
__device__ __align__(16) h16 g_wih_lo[(size_t)G4 * KP2];
__device__ __align__(16) h16 g_whh_h[(size_t)G4 * OUTD];    // reordered
__device__ __align__(16) h16 g_xh[(size_t)TSTEPS * BB * KP2];
__device__ float g_gates_in[(size_t)TSTEPS * BB * G4];      // reordered cols
__device__ __align__(16) h16 g_h0[BB * OUTD];
__device__ __align__(16) h16 g_h1[BB * OUTD];
__device__ float g_c[BB * OUTD];
__device__ __align__(16) float g_part[2][BB][G4];           // split-K partials
__device__ unsigned g_scnt[64];                              // per-ntile tickets

// ------------------------- helpers -------------------------
__device__ __forceinline__ void split_write(float v, h16* hi, h16* lo) {
    h16 h = __float2half(v);
    *hi = h;
    *lo = __float2half(v - __half2float(h));
}

__device__ __forceinline__ void cp16(void* dst, const void* src) {
    unsigned d = (unsigned)__cvta_generic_to_shared(dst);
    asm volatile("cp.async.ca.shared.global [%0], [%1], 16;\n" ::"r"(d), "l"(src));
}

// ------------------------- init + scale -------------------------
__global__ void k_init(const float* __restrict__ boxes) {
    int idx = blockIdx.x * blockDim.x + threadIdx.x;
    if (idx < 64) g_scnt[idx] = 0;
    if (idx < BB) {
        const float* p = boxes + (size_t)idx * 4 * NN;
        float m = -1e30f;
        for (int i = 0; i < 4 * NN; i++) m = fmaxf(m, p[i]);
        g_scale[idx] = m;
    }
    if (idx < BB * OUTD) {
        g_h0[idx] = __float2half(0.f);
        g_c[idx] = 0.f;
    }
}

__global__ void k_head(const float* __restrict__ boxes,
                       const float* __restrict__ att) {
    int idx = blockIdx.x * blockDim.x + threadIdx.x;
    if (idx >= BB * NN) return;
    int b = idx / NN, n = idx - b * NN;
    float inv = 1.f / g_scale[b];
    for (int r = 0; r < 4; r++)
        g_feats[(size_t)b * MIDD * NN + r * NN + n] =
            boxes[(size_t)b * 4 * NN + r * NN + n] * inv;
    float a = att[idx];
    g_feats[(size_t)b * MIDD * NN + 4 * NN + n] = a;
    g_sigatt[idx] = 1.f / (1.f + expf(-a));
}

// ------------------------- fused weight/feature prep ------------------------
#define PN1 ((size_t)512 * FEATD)
#define PN2 ((size_t)G4 * KP2)
#define PN3 ((size_t)G4 * OUTD)
#define PN4 ((size_t)BB * NN * FEATD)
__global__ void k_prep(const float* __restrict__ cw, const float* __restrict__ wih,
                       const float* __restrict__ whh, const float* __restrict__ feat) {
    size_t idx = (size_t)blockIdx.x * blockDim.x + threadIdx.x;
    if (idx < PN1) {
        g_convw_h[idx] = __float2half(cw[idx]);
    } else if (idx < PN1 + PN2) {
        size_t i = idx - PN1;
        int cr = (int)(i / KP2), k = (int)(i - (size_t)cr * KP2);
        int u = cr >> 2, g = cr & 3;
        float v = (k < MIDD) ? wih[(size_t)(g * OUTD + u) * MIDD + k] : 0.f;
        split_write(v, &g_wih_hi[i], &g_wih_lo[i]);
    } else if (idx < PN1 + PN2 + PN3) {
        size_t i = idx - PN1 - PN2;
        int cr = (int)(i / OUTD), k = (int)(i - (size_t)cr * OUTD);
        int u = cr >> 2, g = cr & 3;
        g_whh_h[i] = __float2half(whh[(size_t)(g * OUTD + u) * OUTD + k]);
    } else if (idx < PN1 + PN2 + PN3 + PN4) {
        size_t i = idx - PN1 - PN2 - PN3;
        split_write(feat[i], &g_feat_hi[i], &g_feat_lo[i]);
    }
}

// ------------------------- fp16 GEMM core: 128x64 tile, k-chunk 64 ----------
// NT=2: C = Ah * (Bh+Bl)^T ; NT=1: C = Ah * Bh^T.  STG: stage stride bytes.
template <int NT, int STG>
__device__ __forceinline__ float* gemm_core(
    const h16* __restrict__ Ah,
    const h16* __restrict__ Bh, const h16* __restrict__ Bl,
    int lda, int ldb, int nch, int m0, int n0, int kbeg, char* sm)
{
    const int t = threadIdx.x, w = t >> 5;
    const int wm = w >> 1, wn = w & 1;       // 4 x 2 warp grid

    wmma::fragment<wmma::accumulator, 16, 16, 16, float> acc[2][2];
#pragma unroll
    for (int i = 0; i < 2; i++)
#pragma unroll
        for (int j = 0; j < 2; j++) wmma::fill_fragment(acc[i][j], 0.f);

    auto issue = [&](int jc) {
        char* st = sm + (jc % 3) * STG;
        int k0 = kbeg + jc * 64;
        const int NSEG = (NT == 2) ? 8 : 6;
#pragma unroll
        for (int u = 0; u < NSEG; u++) {
            int seg = t + u * 256;
            if (seg < 1024) {
                int row = seg >> 3, s = seg & 7;
                cp16(st + C_OA + row * 144 + s * 16,
                     Ah + (size_t)(m0 + row) * lda + k0 + s * 8);
            } else if (seg < 1536) {
                int x = seg - 1024;
                int row = x >> 3, s = x & 7;
                cp16(st + C_OBH + row * 144 + s * 16,
                     Bh + (size_t)(n0 + row) * ldb + k0 + s * 8);
            } else {
                int x = seg - 1536;
                int row = x >> 3, s = x & 7;
                cp16(st + C_OBL + row * 144 + s * 16,
                     Bl + (size_t)(n0 + row) * ldb + k0 + s * 8);
            }
        }
        asm volatile("cp.async.commit_group;\n" ::: "memory");
    };

    issue(0);
    issue(1);
    for (int i = 0; i < nch; i++) {
        if (i < nch - 1)
            asm volatile("cp.async.wait_group 1;\n" ::: "memory");
        else
            asm volatile("cp.async.wait_group 0;\n" ::: "memory");
        __syncthreads();
        if (i + 2 < nch) issue(i + 2);

        char* st = sm + (i % 3) * STG;
        h16* sA = (h16*)(st + C_OA);
        h16* sBh = (h16*)(st + C_OBH);
        h16* sBl = (h16*)(st + C_OBL);
#pragma unroll
        for (int ks = 0; ks < 4; ks++) {
            const int kk = ks * 16;
            wmma::fragment<wmma::matrix_a, 16, 16, 16, h16, wmma::row_major> a[2];
            wmma::fragment<wmma::matrix_b, 16, 16, 16, h16, wmma::col_major> bh[2];
#pragma unroll
            for (int i2 = 0; i2 < 2; i2++) {
                wmma::load_matrix_sync(a[i2], &sA[(wm * 32 + i2 * 16) * C_LD + kk], C_LD);
                wmma::load_matrix_sync(bh[i2], &sBh[(wn * 32 + i2 * 16) * C_LD + kk], C_LD);
            }
#pragma unroll
            for (int i2 = 0; i2 < 2; i2++)
#pragma unroll
                for (int j2 = 0; j2 < 2; j2++)
                    wmma::mma_sync(acc[i2][j2], a[i2], bh[j2], acc[i2][j2]);
            if (NT == 2) {
                wmma::fragment<wmma::matrix_b, 16, 16, 16, h16, wmma::col_major> bl[2];
#pragma unroll
                for (int i2 = 0; i2 < 2; i2++)
                    wmma::load_matrix_sync(bl[i2], &sBl[(wn * 32 + i2 * 16) * C_LD + kk], C_LD);
#pragma unroll
                for (int i2 = 0; i2 < 2; i2++)
#pragma unroll
                    for (int j2 = 0; j2 < 2; j2++)
                        wmma::mma_sync(acc[i2][j2], a[i2], bl[j2], acc[i2][j2]);
            }
        }
    }
    __syncthreads();
    float* Cs = (float*)sm;   // 32KB, aliases consumed stages
#pragma unroll
    for (int i2 = 0; i2 < 2; i2++)
#pragma unroll
        for (int j2 = 0; j2 < 2; j2++)
            wmma::store_matrix_sync(&Cs[(wm * 32 + i2 * 16) * 64 + wn * 32 + j2 * 16],
                                    acc[i2][j2], 64, wmma::mem_row_major);
    __syncthreads();
    return Cs;
}

// ------------------------- conv GEMM -------------------------
__global__ __launch_bounds__(256) void k_conv(const float* __restrict__ convb) {
    extern __shared__ char sm[];
    int m0 = blockIdx.x * 128, n0 = blockIdx.y * 64;
    float* Cs = gemm_core<2, STG2>(g_convw_h, g_feat_hi, g_feat_lo,
                                   FEATD, FEATD, FEATD / 64, m0, n0, 0, sm);
    for (int idx = threadIdx.x; idx < 128 * 64; idx += 256) {
        int r = idx >> 6, cc = idx & 63;
        int m = m0 + r, col = n0 + cc;
        int b = col / NN, n = col - b * NN;
        g_feats[(size_t)b * MIDD * NN + (5 + m) * NN + n] = Cs[idx] + convb[m];
    }
}

// ------------------------- input-gate GEMM -------------------------
__global__ __launch_bounds__(256) void k_gin(const float* __restrict__ bih,
                                             const float* __restrict__ bhh) {
    extern __shared__ char sm[];
    int m0 = blockIdx.x * 128, n0 = blockIdx.y * 64;
    float* Cs = gemm_core<2, STG2>(g_xh, g_wih_hi, g_wih_lo,
                                   KP2, KP2, KP2 / 64, m0, n0, 0, sm);
    for (int idx = threadIdx.x; idx < 128 * 64; idx += 256) {
        int r = idx >> 6, cc = idx & 63;
        int row = m0 + r, col = n0 + cc;
        int orig = (col & 3) * OUTD + (col >> 2);
        g_gates_in[(size_t)row * G4 + col] = Cs[idx] + bih[orig] + bhh[orig];
    }
}

// ------------------------- recurrent step: split-K2 + fused update ----------
__global__ __launch_bounds__(256) void k_step(int s, float* __restrict__ outc) {
    extern __shared__ char sm[];
    const int kz = blockIdx.x;          // 0/1: K half
    const int ntile = blockIdx.y;       // 64 tiles of N=64
    const int n0 = ntile * 64;
    const int t = threadIdx.x;

    const h16* hin = (s & 1) ? g_h1 : g_h0;
    h16* hout = (s & 1) ? g_h0 : g_h1;

    float* Cs = gemm_core<1, STG1>(hin, g_whh_h, g_whh_h,
                                   OUTD, OUTD, 8, 0, n0, kz * 512, sm);

    // publish this half's partial
    float4* dst4 = (float4*)&g_part[kz][0][n0];
    const float4* Cs4 = (const float4*)Cs;
    for (int p = t; p < 2048; p += 256)
        dst4[(p >> 4) * (G4 / 4) + (p & 15)] = Cs4[p];
    __threadfence();

    __shared__ unsigned s_last;
    if (t == 0) s_last = (atomicAdd(&g_scnt[ntile], 1u) == 1u);
    __syncthreads();
    if (!s_last) return;
    __threadfence();  // acquire: see peer's partial

    const int oz = kz ^ 1;
    const float* gin = g_gates_in + (size_t)s * BB * G4;
    for (int p = t; p < 2048; p += 256) {
        int b = p >> 4, lu = p & 15;
        float4 mine = Cs4[p];
        float4 oth = *(const float4*)&g_part[oz][b][n0 + lu * 4];
        float4 gv = *(const float4*)(gin + (size_t)b * G4 + n0 + lu * 4);
        float ig = mine.x + oth.x + gv.x;
        float fg = mine.y + oth.y + gv.y;
        float gg = mine.z + oth.z + gv.z;
        float og = mine.w + oth.w + gv.w;
        float si = 1.f / (1.f + expf(-ig));
        float sf = 1.f / (1.f + expf(-fg));
        float so = 1.f / (1.f + expf(-og));
        int u = (n0 >> 2) + lu;
        int ci = b * OUTD + u;
        float c = sf * g_c[ci] + si * tanhf(gg);
        g_c[ci] = c;
        hout[ci] = __float2half(so * tanhf(c));
        if (outc) outc[ci] = c;
    }
    if (t == 0) g_scnt[ntile] = 0;   // re-arm for next step's launch
}

// ------------------------- fused skew + assignment + mix --------------------
__global__ __launch_bounds__(512) void k_sa(const float* __restrict__ wx,
                                            const float* __restrict__ wy,
                                            const float* __restrict__ b1,
                                            const float* __restrict__ w2,
                                            const float* __restrict__ b2p,
                                            const float* __restrict__ lrp) {
    extern __shared__ float S[];
    int b = blockIdx.x, t = threadIdx.x;
    const float* fb = g_feats + (size_t)b * MIDD * NN;

    // ---- phase 1: skew hx/hy into smem ----
    {
        int h = t & 127, g = t >> 7;     // 4 col-groups of 9
        float ax[9], ay[9];
#pragma unroll
        for (int n = 0; n < 9; n++) { ax[n] = 0.f; ay[n] = 0.f; }
        for (int mc = 0; mc < MIDD; mc += 32) {
            int mlen = min(32, MIDD - mc);
            for (int i = t; i < mlen * NN; i += 512) S[SA_SF + i] = fb[mc * NN + i];
            if (g == 0) {
                for (int j = 0; j < mlen; j++)
                    S[SA_SWX + h * 33 + j] = wx[(size_t)h * MIDD + mc + j];
            } else if (g == 1) {
                for (int j = 0; j < mlen; j++)
                    S[SA_SWY + h * 33 + j] = wy[(size_t)h * MIDD + mc + j];
            }
            __syncthreads();
            for (int j = 0; j < mlen; j++) {
                float wxv = S[SA_SWX + h * 33 + j];
                float wyv = S[SA_SWY + h * 33 + j];
                const float* sr = &S[SA_SF + j * NN + g * 9];
#pragma unroll
                for (int n = 0; n < 9; n++) {
                    float fv = sr[n];
                    ax[n] += wxv * fv;
                    ay[n] += wyv * fv;
                }
            }
            __syncthreads();
        }
#pragma unroll
        for (int n = 0; n < 9; n++) {
            S[SA_HX + h * NN + g * 9 + n] = ax[n];
            S[SA_HY + h * NN + g * 9 + n] = ay[n];
        }
    }
    if (t < 128) { S[SA_W2 + t] = w2[t]; S[SA_B1 + t] = b1[t]; }
    if (t < 36) S[SA_SA + t] = g_sigatt[b * NN + t];
    __syncthreads();

    // ---- phase 2: skew scores + antisymmetrize ----
    float b2v = b2p[0];
    for (int p = t; p < 1296; p += 512) {
        int i = p / 36, j = p - i * 36;
        float s = 0.f;
#pragma unroll 8
        for (int h = 0; h < HIDD; h++) {
            float v = S[SA_HX + h * NN + i] + S[SA_HY + h * NN + j] + S[SA_B1 + h];
            s += S[SA_W2 + h] * fmaxf(v, 0.f);
        }
        S[SA_OUT + p] = s + b2v;
    }
    __syncthreads();
    for (int p = t; p < 1296; p += 512) {
        int i = p / 36, j = p - i * 36;
        S[SA_CS + p] = S[SA_OUT + p] - S[SA_OUT + j * 36 + i];
        S[SA_LG + p] = 0.f;
    }
    __syncthreads();

    // ---- phase 3: 3-iter assignment ----
    float lrabs = fabsf(lrp[0]);
    for (int it = 0; it < 3; it++) {
        if (t < 36) {
            float mx = -1e30f;
            for (int j = 0; j < 36; j++) mx = fmaxf(mx, S[SA_LG + t * 36 + j]);
            float sum = 0.f;
            for (int j = 0; j < 36; j++) {
                float e = expf(S[SA_LG + t * 36 + j] - mx);
                S[SA_PS + t * 36 + j] = e;
                sum += e;
            }
            float inv = 1.f / sum;
            for (int j = 0; j < 36; j++) S[SA_PS + t * 36 + j] *= inv;
        }
        __syncthreads();
        if (t < 36) {
            int l = t;
            float tot = 0.f;
            for (int i = 0; i < 36; i++) tot += S[SA_PS + i * 36 + l];
            float run = 0.f;
            for (int i = 0; i < 36; i++) {
                float p = S[SA_PS + i * 36 + l];
                run += p;
                S[SA_DS + i * 36 + l] = tot - 2.f * run + p;
            }
        }
        __syncthreads();
        for (int p = t; p < 1296; p += 512) {
            int i = p / 36, j = p - i * 36;
            float gsum = 0.f;
#pragma unroll
            for (int l = 0; l < 36; l++)
                gsum += S[SA_DS + i * 36 + l] * S[SA_CS + j * 36 + l];
            S[SA_LG + p] -= lrabs * gsum;
        }
        __syncthreads();
    }
    if (t < 36) {
        float mx = -1e30f;
        for (int j = 0; j < 36; j++) mx = fmaxf(mx, S[SA_LG + t * 36 + j]);
        float sum = 0.f;
        for (int j = 0; j < 36; j++) {
            float e = expf(S[SA_LG + t * 36 + j] - mx);
            S[SA_PS + t * 36 + j] = e;
            sum += e;
        }
        float inv = 1.f / sum;
        for (int j = 0; j < 36; j++) S[SA_PS + t * 36 + j] *= inv;
    }
    __syncthreads();

    // ---- phase 4: permutation mix -> x_seq fp16 ----
    for (int p = t; p < MIDD * NN; p += 512) {
        int c = p / 36, i = p - c * 36;
        float s = 0.f;
#pragma unroll
        for (int l = 0; l < 36; l++)
            s += fb[c * 36 + l] * S[SA_SA + l] * S[SA_PS + i * 36 + l];
        g_xh[((size_t)i * BB + b) * KP2 + c] = __float2half(s);
    }
    for (int p = t; p < (KP2 - MIDD) * NN; p += 512) {
        int c = MIDD + p / 36, i = p % 36;
        g_xh[((size_t)i * BB + b) * KP2 + c] = __float2half(0.f);
    }
}

// ------------------------- launch -------------------------
extern "C" void kernel_launch(void* const* d_in, const int* in_sizes, int n_in,
                              void* d_out, int out_size) {
    const float* boxes     = (const float*)d_in[0];
    const float* attention = (const float*)d_in[1];
    const float* features  = (const float*)d_in[2];
    const float* conv_w    = (const float*)d_in[3];
    const float* conv_b    = (const float*)d_in[4];
    const float* skew_wx   = (const float*)d_in[5];
    const float* skew_wy   = (const float*)d_in[6];
    const float* skew_b1   = (const float*)d_in[7];
    const float* skew_w2   = (const float*)d_in[8];
    const float* skew_b2   = (const float*)d_in[9];
    const float* w_ih      = (const float*)d_in[10];
    const float* w_hh      = (const float*)d_in[11];
    const float* b_ih      = (const float*)d_in[12];
    const float* b_hh      = (const float*)d_in[13];
    const float* lr        = (const float*)d_in[14];

    static int attr_done = 0;
    if (!attr_done) {
        cudaFuncSetAttribute(k_conv, cudaFuncAttributeMaxDynamicSharedMemorySize, DYN2);
        cudaFuncSetAttribute(k_gin,  cudaFuncAttributeMaxDynamicSharedMemorySize, DYN2);
        cudaFuncSetAttribute(k_step, cudaFuncAttributeMaxDynamicSharedMemorySize, DYN1);
        cudaFuncSetAttribute(k_sa,   cudaFuncAttributeMaxDynamicSharedMemorySize, SA_DYN);
        attr_done = 1;
    }

    k_init<<<(BB * OUTD + 255) / 256, 256>>>(boxes);
    k_head<<<(BB * NN + 255) / 256, 256>>>(boxes, attention);
    {
        size_t total = PN1 + PN2 + PN3 + PN4;
        k_prep<<<(unsigned)((total + 511) / 512), 512>>>(conv_w, w_ih, w_hh, features);
    }
    k_conv<<<dim3(4, 72), 256, DYN2>>>(conv_b);
    k_sa<<<BB, 512, SA_DYN>>>(skew_wx, skew_wy, skew_b1, skew_w2, skew_b2, lr);
    k_gin<<<dim3(36, 64), 256, DYN2>>>(b_ih, b_hh);

    for (int s = 0; s < TSTEPS; s++) {
        k_step<<<dim3(2, 64), 256, DYN1>>>(s, s == TSTEPS - 1 ? (float*)d_out : nullptr);
    }
}

// round 9
// speedup vs baseline: 1.5906x; 1.0261x over previous
#include <cuda_runtime.h>
#include <cuda_fp16.h>
#include <mma.h>
#include <cstdint>

using namespace nvcuda;
typedef __half h16;

#define BB   128
#define NN   36
#define FEATD 2048
#define MIDD 517
#define HIDD 128
#define OUTD 1024
#define G4   4096
#define KP2  576
#define TSTEPS 36

// ---- small core (steps): 128x64 tile, 8 warps, k-chunk 64, 3-stage ----
#define C_LD   72
#define C_OA   0
#define C_OBH  18432
#define C_OBL  27648
#define STG1   27648
#define DYN1   (3 * STG1)                // 82944

// ---- big core (conv/gin): 128x128 tile, 16 warps, k-chunk 64, 2-stage ----
#define D_OA   0
#define D_OBH  18432
#define D_OBL  36864
#define D_STG  55296
#define DYN2   (2 * D_STG)               // 110592

// ---- fused skew+assign smem layout (floats) ----
#define SA_SF   0
#define SA_SWX  1152
#define SA_SWY  5376
#define SA_HX   9600
#define SA_HY   14208
#define SA_OUT  18816
#define SA_CS   20112
#define SA_LG   21408
#define SA_PS   22704
#define SA_DS   24000
#define SA_SA   25296
#define SA_W2   25332
#define SA_B1   25460
#define SA_TOT  25588
#define SA_DYN  (SA_TOT * 4)

// ------------------------- scratch -------------------------
__device__ float g_scale[BB];
__device__ float g_sigatt[BB * NN];
__device__ float g_feats[BB * MIDD * NN];                 // [b][m][n] fp32

__device__ __align__(16) h16 g_feat_hi[(size_t)BB * NN * FEATD];
__device__ __align__(16) h16 g_feat_lo[(size_t)BB * NN * FEATD];
__device__ __align__(16) h16 g_convw_h[512 * FEATD];
__device__ __align__(16) h16 g_wih_hi[(size_t)G4 * KP2];    // col = u*4+g
__device__ __align__(16) h16 g_wih_lo[(size_t)G4 * KP2];
__device__ __align__(16) h16 g_whh_h[(size_t)G4 * OUTD];    // reordered
__device__ __align__(16) h16 g_xh[(size_t)TSTEPS * BB * KP2];
__device__ float g_gates_in[(size_t)TSTEPS * BB * G4];      // reordered cols
__device__ __align__(16) h16 g_h0[BB * OUTD];
__device__ __align__(16) h16 g_h1[BB * OUTD];
__device__ float g_c[BB * OUTD];
__device__ __align__(16) float g_part[2][BB][G4];           // split-K partials
__device__ unsigned g_scnt[64];                              // per-ntile tickets

// ------------------------- helpers -------------------------
__device__ __forceinline__ void split_write(float v, h16* hi, h16* lo) {
    h16 h = __float2half(v);
    *hi = h;
    *lo = __float2half(v - __half2float(h));
}

__device__ __forceinline__ void cp16(void* dst, const void* src) {
    unsigned d = (unsigned)__cvta_generic_to_shared(dst);
    asm volatile("cp.async.ca.shared.global [%0], [%1], 16;\n" ::"r"(d), "l"(src));
}

// ------------------------- init + scale -------------------------
__global__ void k_init(const float* __restrict__ boxes) {
    int idx = blockIdx.x * blockDim.x + threadIdx.x;
    if (idx < 64) g_scnt[idx] = 0;
    if (idx < BB) {
        const float* p = boxes + (size_t)idx * 4 * NN;
        float m = -1e30f;
        for (int i = 0; i < 4 * NN; i++) m = fmaxf(m, p[i]);
        g_scale[idx] = m;
    }
    if (idx < BB * OUTD) {
        g_h0[idx] = __float2half(0.f);
        g_c[idx] = 0.f;
    }
}

__global__ void k_head(const float* __restrict__ boxes,
                       const float* __restrict__ att) {
    int idx = blockIdx.x * blockDim.x + threadIdx.x;
    if (idx >= BB * NN) return;
    int b = idx / NN, n = idx - b * NN;
    float inv = 1.f / g_scale[b];
    for (int r = 0; r < 4; r++)
        g_feats[(size_t)b * MIDD * NN + r * NN + n] =
            boxes[(size_t)b * 4 * NN + r * NN + n] * inv;
    float a = att[idx];
    g_feats[(size_t)b * MIDD * NN + 4 * NN + n] = a;
    g_sigatt[idx] = 1.f / (1.f + expf(-a));
}

// ------------------------- fused weight/feature prep ------------------------
#define PN1 ((size_t)512 * FEATD)
#define PN2 ((size_t)G4 * KP2)
#define PN3 ((size_t)G4 * OUTD)
#define PN4 ((size_t)BB * NN * FEATD)
__global__ void k_prep(const float* __restrict__ cw, const float* __restrict__ wih,
                       const float* __restrict__ whh, const float* __restrict__ feat) {
    size_t idx = (size_t)blockIdx.x * blockDim.x + threadIdx.x;
    if (idx < PN1) {
        g_convw_h[idx] = __float2half(cw[idx]);
    } else if (idx < PN1 + PN2) {
        size_t i = idx - PN1;
        int cr = (int)(i / KP2), k = (int)(i - (size_t)cr * KP2);
        int u = cr >> 2, g = cr & 3;
        float v = (k < MIDD) ? wih[(size_t)(g * OUTD + u) * MIDD + k] : 0.f;
        split_write(v, &g_wih_hi[i], &g_wih_lo[i]);
    } else if (idx < PN1 + PN2 + PN3) {
        size_t i = idx - PN1 - PN2;
        int cr = (int)(i / OUTD), k = (int)(i - (size_t)cr * OUTD);
        int u = cr >> 2, g = cr & 3;
        g_whh_h[i] = __float2half(whh[(size_t)(g * OUTD + u) * OUTD + k]);
    } else if (idx < PN1 + PN2 + PN3 + PN4) {
        size_t i = idx - PN1 - PN2 - PN3;
        split_write(feat[i], &g_feat_hi[i], &g_feat_lo[i]);
    }
}

// ------------------------- big core: 128x128, 16 warps, 2-stage -------------
// C = Ah[m0:+128,k] * (Bh+Bl)[n0:+128,k]^T   (fp32 acc)
__device__ __forceinline__ float* gemm_big(
    const h16* __restrict__ Ah,
    const h16* __restrict__ Bh, const h16* __restrict__ Bl,
    int lda, int ldb, int nch, int m0, int n0, char* sm)
{
    const int t = threadIdx.x, w = t >> 5;
    const int wm = w >> 2, wn = w & 3;       // 4 x 4 warp grid

    wmma::fragment<wmma::accumulator, 16, 16, 16, float> acc[2][2];
#pragma unroll
    for (int i = 0; i < 2; i++)
#pragma unroll
        for (int j = 0; j < 2; j++) wmma::fill_fragment(acc[i][j], 0.f);

    auto issue = [&](int jc) {
        char* st = sm + (jc & 1) * D_STG;
        int k0 = jc * 64;
#pragma unroll
        for (int u = 0; u < 6; u++) {
            int seg = t + u * 512;
            if (seg < 1024) {
                int row = seg >> 3, s = seg & 7;
                cp16(st + D_OA + row * 144 + s * 16,
                     Ah + (size_t)(m0 + row) * lda + k0 + s * 8);
            } else if (seg < 2048) {
                int x = seg - 1024;
                int row = x >> 3, s = x & 7;
                cp16(st + D_OBH + row * 144 + s * 16,
                     Bh + (size_t)(n0 + row) * ldb + k0 + s * 8);
            } else {
                int x = seg - 2048;
                int row = x >> 3, s = x & 7;
                cp16(st + D_OBL + row * 144 + s * 16,
                     Bl + (size_t)(n0 + row) * ldb + k0 + s * 8);
            }
        }
        asm volatile("cp.async.commit_group;\n" ::: "memory");
    };

    issue(0);
    for (int i = 0; i < nch; i++) {
        asm volatile("cp.async.wait_group 0;\n" ::: "memory");
        __syncthreads();
        if (i + 1 < nch) issue(i + 1);

        char* st = sm + (i & 1) * D_STG;
        h16* sA = (h16*)(st + D_OA);
        h16* sBh = (h16*)(st + D_OBH);
        h16* sBl = (h16*)(st + D_OBL);
#pragma unroll
        for (int ks = 0; ks < 4; ks++) {
            const int kk = ks * 16;
            wmma::fragment<wmma::matrix_a, 16, 16, 16, h16, wmma::row_major> a[2];
            wmma::fragment<wmma::matrix_b, 16, 16, 16, h16, wmma::col_major> bh[2];
#pragma unroll
            for (int i2 = 0; i2 < 2; i2++) {
                wmma::load_matrix_sync(a[i2], &sA[(wm * 32 + i2 * 16) * C_LD + kk], C_LD);
                wmma::load_matrix_sync(bh[i2], &sBh[(wn * 32 + i2 * 16) * C_LD + kk], C_LD);
            }
#pragma unroll
            for (int i2 = 0; i2 < 2; i2++)
#pragma unroll
                for (int j2 = 0; j2 < 2; j2++)
                    wmma::mma_sync(acc[i2][j2], a[i2], bh[j2], acc[i2][j2]);
            wmma::fragment<wmma::matrix_b, 16, 16, 16, h16, wmma::col_major> bl[2];
#pragma unroll
            for (int i2 = 0; i2 < 2; i2++)
                wmma::load_matrix_sync(bl[i2], &sBl[(wn * 32 + i2 * 16) * C_LD + kk], C_LD);
#pragma unroll
            for (int i2 = 0; i2 < 2; i2++)
#pragma unroll
                for (int j2 = 0; j2 < 2; j2++)
                    wmma::mma_sync(acc[i2][j2], a[i2], bl[j2], acc[i2][j2]);
        }
    }
    __syncthreads();
    float* Cs = (float*)sm;   // 64KB, aliases both (consumed) stages
#pragma unroll
    for (int i2 = 0; i2 < 2; i2++)
#pragma unroll
        for (int j2 = 0; j2 < 2; j2++)
            wmma::store_matrix_sync(&Cs[(wm * 32 + i2 * 16) * 128 + wn * 32 + j2 * 16],
                                    acc[i2][j2], 128, wmma::mem_row_major);
    __syncthreads();
    return Cs;
}

// ------------------------- small core: 128x64, 8 warps, 3-stage -------------
__device__ __forceinline__ float* gemm_core(
    const h16* __restrict__ Ah, const h16* __restrict__ Bh,
    int lda, int ldb, int nch, int m0, int n0, int kbeg, char* sm)
{
    const int t = threadIdx.x, w = t >> 5;
    const int wm = w >> 1, wn = w & 1;

    wmma::fragment<wmma::accumulator, 16, 16, 16, float> acc[2][2];
#pragma unroll
    for (int i = 0; i < 2; i++)
#pragma unroll
        for (int j = 0; j < 2; j++) wmma::fill_fragment(acc[i][j], 0.f);

    auto issue = [&](int jc) {
        char* st = sm + (jc % 3) * STG1;
        int k0 = kbeg + jc * 64;
#pragma unroll
        for (int u = 0; u < 6; u++) {
            int seg = t + u * 256;
            if (seg < 1024) {
                int row = seg >> 3, s = seg & 7;
                cp16(st + C_OA + row * 144 + s * 16,
                     Ah + (size_t)(m0 + row) * lda + k0 + s * 8);
            } else {
                int x = seg - 1024;
                int row = x >> 3, s = x & 7;
                cp16(st + C_OBH + row * 144 + s * 16,
                     Bh + (size_t)(n0 + row) * ldb + k0 + s * 8);
            }
        }
        asm volatile("cp.async.commit_group;\n" ::: "memory");
    };

    issue(0);
    issue(1);
    for (int i = 0; i < nch; i++) {
        if (i < nch - 1)
            asm volatile("cp.async.wait_group 1;\n" ::: "memory");
        else
            asm volatile("cp.async.wait_group 0;\n" ::: "memory");
        __syncthreads();
        if (i + 2 < nch) issue(i + 2);

        char* st = sm + (i % 3) * STG1;
        h16* sA = (h16*)(st + C_OA);
        h16* sBh = (h16*)(st + C_OBH);
#pragma unroll
        for (int ks = 0; ks < 4; ks++) {
            const int kk = ks * 16;
            wmma::fragment<wmma::matrix_a, 16, 16, 16, h16, wmma::row_major> a[2];
            wmma::fragment<wmma::matrix_b, 16, 16, 16, h16, wmma::col_major> bh[2];
#pragma unroll
            for (int i2 = 0; i2 < 2; i2++) {
                wmma::load_matrix_sync(a[i2], &sA[(wm * 32 + i2 * 16) * C_LD + kk], C_LD);
                wmma::load_matrix_sync(bh[i2], &sBh[(wn * 32 + i2 * 16) * C_LD + kk], C_LD);
            }
#pragma unroll
            for (int i2 = 0; i2 < 2; i2++)
#pragma unroll
                for (int j2 = 0; j2 < 2; j2++)
                    wmma::mma_sync(acc[i2][j2], a[i2], bh[j2], acc[i2][j2]);
        }
    }
    __syncthreads();
    float* Cs = (float*)sm;
#pragma unroll
    for (int i2 = 0; i2 < 2; i2++)
#pragma unroll
        for (int j2 = 0; j2 < 2; j2++)
            wmma::store_matrix_sync(&Cs[(wm * 32 + i2 * 16) * 64 + wn * 32 + j2 * 16],
                                    acc[i2][j2], 64, wmma::mem_row_major);
    __syncthreads();
    return Cs;
}

// ------------------------- conv GEMM (big core) -------------------------
__global__ __launch_bounds__(512) void k_conv(const float* __restrict__ convb) {
    extern __shared__ char sm[];
    int m0 = blockIdx.x * 128, n0 = blockIdx.y * 128;
    float* Cs = gemm_big(g_convw_h, g_feat_hi, g_feat_lo,
                         FEATD, FEATD, FEATD / 64, m0, n0, sm);
    for (int idx = threadIdx.x; idx < 128 * 128; idx += 512) {
        int r = idx >> 7, cc = idx & 127;
        int m = m0 + r, col = n0 + cc;
        int b = col / NN, n = col - b * NN;
        g_feats[(size_t)b * MIDD * NN + (5 + m) * NN + n] = Cs[idx] + convb[m];
    }
}

// ------------------------- input-gate GEMM (big core) -----------------------
__global__ __launch_bounds__(512) void k_gin(const float* __restrict__ bih,
                                             const float* __restrict__ bhh) {
    extern __shared__ char sm[];
    int m0 = blockIdx.x * 128, n0 = blockIdx.y * 128;
    float* Cs = gemm_big(g_xh, g_wih_hi, g_wih_lo,
                         KP2, KP2, KP2 / 64, m0, n0, sm);
    for (int idx = threadIdx.x; idx < 128 * 128; idx += 512) {
        int r = idx >> 7, cc = idx & 127;
        int row = m0 + r, col = n0 + cc;
        int orig = (col & 3) * OUTD + (col >> 2);
        g_gates_in[(size_t)row * G4 + col] = Cs[idx] + bih[orig] + bhh[orig];
    }
}

// ------------------------- recurrent step: split-K2 + fused update ----------
__global__ __launch_bounds__(256) void k_step(int s, float* __restrict__ outc) {
    extern __shared__ char sm[];
    const int kz = blockIdx.x;
    const int ntile = blockIdx.y;
    const int n0 = ntile * 64;
    const int t = threadIdx.x;

    const h16* hin = (s & 1) ? g_h1 : g_h0;
    h16* hout = (s & 1) ? g_h0 : g_h1;

    float* Cs = gemm_core(hin, g_whh_h, OUTD, OUTD, 8, 0, n0, kz * 512, sm);

    float4* dst4 = (float4*)&g_part[kz][0][n0];
    const float4* Cs4 = (const float4*)Cs;
    for (int p = t; p < 2048; p += 256)
        dst4[(p >> 4) * (G4 / 4) + (p & 15)] = Cs4[p];
    __threadfence();

    __shared__ unsigned s_last;
    if (t == 0) s_last = (atomicAdd(&g_scnt[ntile], 1u) == 1u);
    __syncthreads();
    if (!s_last) return;
    __threadfence();

    const int oz = kz ^ 1;
    const float* gin = g_gates_in + (size_t)s * BB * G4;
    for (int p = t; p < 2048; p += 256) {
        int b = p >> 4, lu = p & 15;
        float4 mine = Cs4[p];
        float4 oth = *(const float4*)&g_part[oz][b][n0 + lu * 4];
        float4 gv = *(const float4*)(gin + (size_t)b * G4 + n0 + lu * 4);
        float ig = mine.x + oth.x + gv.x;
        float fg = mine.y + oth.y + gv.y;
        float gg = mine.z + oth.z + gv.z;
        float og = mine.w + oth.w + gv.w;
        float si = 1.f / (1.f + expf(-ig));
        float sf = 1.f / (1.f + expf(-fg));
        float so = 1.f / (1.f + expf(-og));
        int u = (n0 >> 2) + lu;
        int ci = b * OUTD + u;
        float c = sf * g_c[ci] + si * tanhf(gg);
        g_c[ci] = c;
        hout[ci] = __float2half(so * tanhf(c));
        if (outc) outc[ci] = c;
    }
    if (t == 0) g_scnt[ntile] = 0;
}

// ------------------------- fused skew + assignment + mix --------------------
__global__ __launch_bounds__(512) void k_sa(const float* __restrict__ wx,
                                            const float* __restrict__ wy,
                                            const float* __restrict__ b1,
                                            const float* __restrict__ w2,
                                            const float* __restrict__ b2p,
                                            const float* __restrict__ lrp) {
    extern __shared__ float S[];
    int b = blockIdx.x, t = threadIdx.x;
    const float* fb = g_feats + (size_t)b * MIDD * NN;

    {
        int h = t & 127, g = t >> 7;
        float ax[9], ay[9];
#pragma unroll
        for (int n = 0; n < 9; n++) { ax[n] = 0.f; ay[n] = 0.f; }
        for (int mc = 0; mc < MIDD; mc += 32) {
            int mlen = min(32, MIDD - mc);
            for (int i = t; i < mlen * NN; i += 512) S[SA_SF + i] = fb[mc * NN + i];
            if (g == 0) {
                for (int j = 0; j < mlen; j++)
                    S[SA_SWX + h * 33 + j] = wx[(size_t)h * MIDD + mc + j];
            } else if (g == 1) {
                for (int j = 0; j < mlen; j++)
                    S[SA_SWY + h * 33 + j] = wy[(size_t)h * MIDD + mc + j];
            }
            __syncthreads();
            for (int j = 0; j < mlen; j++) {
                float wxv = S[SA_SWX + h * 33 + j];
                float wyv = S[SA_SWY + h * 33 + j];
                const float* sr = &S[SA_SF + j * NN + g * 9];
#pragma unroll
                for (int n = 0; n < 9; n++) {
                    float fv = sr[n];
                    ax[n] += wxv * fv;
                    ay[n] += wyv * fv;
                }
            }
            __syncthreads();
        }
#pragma unroll
        for (int n = 0; n < 9; n++) {
            S[SA_HX + h * NN + g * 9 + n] = ax[n];
            S[SA_HY + h * NN + g * 9 + n] = ay[n];
        }
    }
    if (t < 128) { S[SA_W2 + t] = w2[t]; S[SA_B1 + t] = b1[t]; }
    if (t < 36) S[SA_SA + t] = g_sigatt[b * NN + t];
    __syncthreads();

    float b2v = b2p[0];
    for (int p = t; p < 1296; p += 512) {
        int i = p / 36, j = p - i * 36;
        float s = 0.f;
#pragma unroll 8
        for (int h = 0; h < HIDD; h++) {
            float v = S[SA_HX + h * NN + i] + S[SA_HY + h * NN + j] + S[SA_B1 + h];
            s += S[SA_W2 + h] * fmaxf(v, 0.f);
        }
        S[SA_OUT + p] = s + b2v;
    }
    __syncthreads();
    for (int p = t; p < 1296; p += 512) {
        int i = p / 36, j = p - i * 36;
        S[SA_CS + p] = S[SA_OUT + p] - S[SA_OUT + j * 36 + i];
        S[SA_LG + p] = 0.f;
    }
    __syncthreads();

    float lrabs = fabsf(lrp[0]);
    for (int it = 0; it < 3; it++) {
        if (t < 36) {
            float mx = -1e30f;
            for (int j = 0; j < 36; j++) mx = fmaxf(mx, S[SA_LG + t * 36 + j]);
            float sum = 0.f;
            for (int j = 0; j < 36; j++) {
                float e = expf(S[SA_LG + t * 36 + j] - mx);
                S[SA_PS + t * 36 + j] = e;
                sum += e;
            }
            float inv = 1.f / sum;
            for (int j = 0; j < 36; j++) S[SA_PS + t * 36 + j] *= inv;
        }
        __syncthreads();
        if (t < 36) {
            int l = t;
            float tot = 0.f;
            for (int i = 0; i < 36; i++) tot += S[SA_PS + i * 36 + l];
            float run = 0.f;
            for (int i = 0; i < 36; i++) {
                float p = S[SA_PS + i * 36 + l];
                run += p;
                S[SA_DS + i * 36 + l] = tot - 2.f * run + p;
            }
        }
        __syncthreads();
        for (int p = t; p < 1296; p += 512) {
            int i = p / 36, j = p - i * 36;
            float gsum = 0.f;
#pragma unroll
            for (int l = 0; l < 36; l++)
                gsum += S[SA_DS + i * 36 + l] * S[SA_CS + j * 36 + l];
            S[SA_LG + p] -= lrabs * gsum;
        }
        __syncthreads();
    }
    if (t < 36) {
        float mx = -1e30f;
        for (int j = 0; j < 36; j++) mx = fmaxf(mx, S[SA_LG + t * 36 + j]);
        float sum = 0.f;
        for (int j = 0; j < 36; j++) {
            float e = expf(S[SA_LG + t * 36 + j] - mx);
            S[SA_PS + t * 36 + j] = e;
            sum += e;
        }
        float inv = 1.f / sum;
        for (int j = 0; j < 36; j++) S[SA_PS + t * 36 + j] *= inv;
    }
    __syncthreads();

    for (int p = t; p < MIDD * NN; p += 512) {
        int c = p / 36, i = p - c * 36;
        float s = 0.f;
#pragma unroll
        for (int l = 0; l < 36; l++)
            s += fb[c * 36 + l] * S[SA_SA + l] * S[SA_PS + i * 36 + l];
        g_xh[((size_t)i * BB + b) * KP2 + c] = __float2half(s);
    }
    for (int p = t; p < (KP2 - MIDD) * NN; p += 512) {
        int c = MIDD + p / 36, i = p % 36;
        g_xh[((size_t)i * BB + b) * KP2 + c] = __float2half(0.f);
    }
}

// ------------------------- launch -------------------------
extern "C" void kernel_launch(void* const* d_in, const int* in_sizes, int n_in,
                              void* d_out, int out_size) {
    const float* boxes     = (const float*)d_in[0];
    const float* attention = (const float*)d_in[1];
    const float* features  = (const float*)d_in[2];
    const float* conv_w    = (const float*)d_in[3];
    const float* conv_b    = (const float*)d_in[4];
    const float* skew_wx   = (const float*)d_in[5];
    const float* skew_wy   = (const float*)d_in[6];
    const float* skew_b1   = (const float*)d_in[7];
    const float* skew_w2   = (const float*)d_in[8];
    const float* skew_b2   = (const float*)d_in[9];
    const float* w_ih      = (const float*)d_in[10];
    const float* w_hh      = (const float*)d_in[11];
    const float* b_ih      = (const float*)d_in[12];
    const float* b_hh      = (const float*)d_in[13];
    const float* lr        = (const float*)d_in[14];

    static int attr_done = 0;
    if (!attr_done) {
        cudaFuncSetAttribute(k_conv, cudaFuncAttributeMaxDynamicSharedMemorySize, DYN2);
        cudaFuncSetAttribute(k_gin,  cudaFuncAttributeMaxDynamicSharedMemorySize, DYN2);
        cudaFuncSetAttribute(k_step, cudaFuncAttributeMaxDynamicSharedMemorySize, DYN1);
        cudaFuncSetAttribute(k_sa,   cudaFuncAttributeMaxDynamicSharedMemorySize, SA_DYN);
        attr_done = 1;
    }

    k_init<<<(BB * OUTD + 255) / 256, 256>>>(boxes);
    k_head<<<(BB * NN + 255) / 256, 256>>>(boxes, attention);
    {
        size_t total = PN1 + PN2 + PN3 + PN4;
        k_prep<<<(unsigned)((total + 511) / 512), 512>>>(conv_w, w_ih, w_hh, features);
    }
    k_conv<<<dim3(4, 36), 512, DYN2>>>(conv_b);
    k_sa<<<BB, 512, SA_DYN>>>(skew_wx, skew_wy, skew_b1, skew_w2, skew_b2, lr);
    k_gin<<<dim3(36, 32), 512, DYN2>>>(b_ih, b_hh);

    for (int s = 0; s < TSTEPS; s++) {
        k_step<<<dim3(2, 64), 256, DYN1>>>(s, s == TSTEPS - 1 ? (float*)d_out : nullptr);
    }
}